// round 4
// baseline (speedup 1.0000x reference)
#include <cuda_runtime.h>
#include <cstdint>

// Problem shape (fixed by the dataset problem)
#define BB 4
#define NN 8192
#define CC 3
#define OO 64
#define KK 20
#define PTS   (BB * NN)          // 32768
#define EDGES (PTS * KK)         // 655360
#define NKB   (NN * KK)          // 163840 edges per batch
#define SBLK  512                // stats partial blocks

#define INF_F __int_as_float(0x7f800000)

// ---------------- device scratch (no allocations allowed) ----------------
__device__ float4 g_cand[PTS];          // (x, y, z, sq)
__device__ float  g_A [PTS * OO];       // x · (W1 - W2)^T   (center contribution)
__device__ float  g_Bv[PTS * OO];       // x · W2^T          (neighbor contribution)
__device__ int    g_idx[EDGES];         // knn indices (per-batch, sorted by distance)
__device__ float  g_part[SBLK * 2 * OO];
__device__ float  g_scale[OO];
__device__ float  g_shift[OO];

// ---------------- helpers ----------------

// Reference-parity distance (GPU/ptxas-contracted hypothesis):
//   sq  = fma(x2,x2, fma(x1,x1, x0*x0))          [ptxas -fmad=true fuses the ref's mul+add reduce]
//   dot = fma(z, fma(y, mul(x)))                  [cublas K-ascending FMA chain]
//   d2  = fma(-2, dot, sqn+sqm)  == fl((sqn+sqm) - 2*dot)   [single rounding, 2*dot exact]
__device__ __forceinline__ float d2f(float qx, float qy, float qz, float sqn,
                                     float4 c) {
    float dot = __fmaf_rn(qz, c.z, __fmaf_rn(qy, c.y, __fmul_rn(qx, c.x)));
    return __fmaf_rn(-2.0f, dot, __fadd_rn(sqn, c.w));
}

// Branchless fully-unrolled sorted insert (ascending). Caller guarantees
// d < kd[KK-1]. Ties: new element goes AFTER equal existing ones (strict <),
// which with ascending-index scan order matches lax.top_k stability.
__device__ __forceinline__ void insert20(float (&kd)[KK], int (&ki)[KK],
                                         float d, int m) {
#pragma unroll
    for (int j = KK - 1; j >= 0; --j) {
        bool ltj = d < kd[j];
        if (ltj) {
            bool ltp = (j > 0) ? (d < kd[j - 1]) : false;
            kd[j] = ltp ? kd[j - 1] : d;
            ki[j] = ltp ? ki[j - 1] : m;
        }
    }
}

// ---------------- kernel 1: per-point precompute ----------------
__global__ void k_prep(const float* __restrict__ x, const float* __restrict__ W) {
    __shared__ float sW[OO * 6];
    int tid = threadIdx.x;
    for (int i = tid; i < OO * 6; i += blockDim.x) sW[i] = W[i];
    __syncthreads();

    int p = blockIdx.x * blockDim.x + tid;
    float x0 = x[p * 3 + 0], x1 = x[p * 3 + 1], x2 = x[p * 3 + 2];
    // sq as FMA chain (reference-parity, see header comment)
    float sq = __fmaf_rn(x2, x2, __fmaf_rn(x1, x1, __fmul_rn(x0, x0)));
    g_cand[p] = make_float4(x0, x1, x2, sq);

#pragma unroll 8
    for (int o = 0; o < OO; ++o) {
        float w0 = sW[o * 6 + 0], w1 = sW[o * 6 + 1], w2 = sW[o * 6 + 2];
        float w3 = sW[o * 6 + 3], w4 = sW[o * 6 + 4], w5 = sW[o * 6 + 5];
        g_Bv[p * OO + o] = w3 * x0 + w4 * x1 + w5 * x2;
        g_A [p * OO + o] = (w0 - w3) * x0 + (w1 - w4) * x1 + (w2 - w5) * x2;
    }
}

// ---------------- kernel 2: brute-force exact kNN ----------------
// 1 thread = 1 query. Candidate tiles staged in smem (broadcast reads).
// Accepted candidates go to a per-lane smem buffer; batched flush into a
// register-resident sorted top-20 when any lane's buffer reaches 8.
__global__ void __launch_bounds__(128) k_knn(int* __restrict__ outidx) {
    __shared__ float4 tile[1024];            // 16 KB
    __shared__ uint2  sbuf[128][16];         // 16 KB, per-lane buffers

    const int tid = threadIdx.x;
    const int pb  = blockIdx.y * NN;
    const int q   = blockIdx.x * 128 + tid;

    float4 qc = g_cand[pb + q];
    const float qx = qc.x, qy = qc.y, qz = qc.z, sqn = qc.w;

    float kd[KK];
    int   ki[KK];
#pragma unroll
    for (int j = 0; j < KK; ++j) { kd[j] = INF_F; ki[j] = 0; }
    float tau = INF_F;
    int   cnt = 0;

    for (int t0 = 0; t0 < NN; t0 += 1024) {
        __syncthreads();
#pragma unroll
        for (int i = 0; i < 1024; i += 128) tile[i + tid] = g_cand[pb + t0 + i + tid];
        __syncthreads();

        int jstart = 0;
        if (t0 == 0) {
            // warm-up: direct insert of first 32 candidates (fills the list,
            // establishes a real tau, avoids early buffer-flush churn)
            for (int j = 0; j < 32; ++j) {
                float d2 = d2f(qx, qy, qz, sqn, tile[j]);
                if (d2 < kd[KK - 1]) insert20(kd, ki, d2, j);
            }
            tau = kd[KK - 1];
            jstart = 32;
        }

        for (int j = jstart; j < 1024; j += 8) {
#pragma unroll
            for (int u = 0; u < 8; ++u) {
                float4 c  = tile[j + u];
                float  d2 = d2f(qx, qy, qz, sqn, c);
                if (d2 < tau) {
                    sbuf[tid][cnt] = make_uint2(__float_as_uint(d2),
                                                (unsigned)(t0 + j + u));
                    cnt++;
                }
            }
            if (__any_sync(0xFFFFFFFFu, cnt >= 8)) {
                for (int u2 = 0; u2 < cnt; ++u2) {
                    uint2 e = sbuf[tid][u2];
                    float d = __uint_as_float(e.x);
                    if (d < kd[KK - 1]) insert20(kd, ki, d, (int)e.y);
                }
                cnt = 0;
                tau = kd[KK - 1];
            }
        }
    }
    // drain
    for (int u2 = 0; u2 < cnt; ++u2) {
        uint2 e = sbuf[tid][u2];
        float d = __uint_as_float(e.x);
        if (d < kd[KK - 1]) insert20(kd, ki, d, (int)e.y);
    }

#pragma unroll
    for (int j = 0; j < KK; ++j) outidx[(pb + q) * KK + j] = ki[j];
}

// ---------------- kernel 3: BN partial stats ----------------
// block = 64 threads (1 thread per channel o), each block covers 64 point-rows
// (= 1280 edges). h = A[n,o] + Bv[m,o]; accumulate sum / sumsq.
__global__ void k_stats(const int* __restrict__ idx) {
    int o   = threadIdx.x;
    int pn0 = blockIdx.x * (PTS / SBLK);   // 64 rows per block
    float s = 0.0f, s2 = 0.0f;
    for (int pn = pn0; pn < pn0 + (PTS / SBLK); ++pn) {
        float a     = g_A[pn * OO + o];
        int   nbase = (pn >> 13) << 13;    // batch base (NN = 8192)
        const int* ip = idx + pn * KK;
#pragma unroll
        for (int j = 0; j < KK; ++j) {
            int   m = __ldg(ip + j);
            float h = a + g_Bv[(nbase + m) * OO + o];
            s  += h;
            s2  = __fmaf_rn(h, h, s2);
        }
    }
    g_part[blockIdx.x * (2 * OO) + o]      = s;
    g_part[blockIdx.x * (2 * OO) + OO + o] = s2;
}

// ---------------- kernel 4: reduce + BN coefficients ----------------
__global__ void k_reduce(const float* __restrict__ gamma,
                         const float* __restrict__ beta) {
    int o = threadIdx.x;  // 64
    double s = 0.0, s2 = 0.0;
    for (int i = 0; i < SBLK; ++i) {
        s  += (double)g_part[i * (2 * OO) + o];
        s2 += (double)g_part[i * (2 * OO) + OO + o];
    }
    const double cnt  = (double)EDGES;
    double mean = s / cnt;
    double var  = s2 / cnt - mean * mean;   // biased, matches jnp.var
    double sc   = (double)gamma[o] / sqrt(var + 1e-5);
    g_scale[o] = (float)sc;
    g_shift[o] = (float)((double)beta[o] - mean * sc);
}

// ---------------- kernel 5: output (fused conv + BN + relu + transpose) ----
// block = 128 threads, 1 thread per edge; stage (64 x 128) tile in smem, then
// write each channel row coalesced into the (B, O, N*k) output.
__global__ void __launch_bounds__(128) k_out(const int* __restrict__ idx,
                                             float* __restrict__ out) {
    __shared__ float stage[OO * 128];   // 32 KB
    __shared__ float ssc[OO], ssh[OO];
    int tid = threadIdx.x;
    if (tid < OO) { ssc[tid] = g_scale[tid]; ssh[tid] = g_shift[tid]; }
    __syncthreads();

    int b  = blockIdx.y;
    int e0 = blockIdx.x * 128;          // within-batch edge offset
    int el = e0 + tid;
    int nl = el / KK;
    int j  = el - nl * KK;
    int pn = b * NN + nl;
    int m  = idx[pn * KK + j];

    const float4* A4 = (const float4*)(g_A  + (size_t)pn * OO);
    const float4* B4 = (const float4*)(g_Bv + ((size_t)(b * NN + m)) * OO);

#pragma unroll
    for (int o4 = 0; o4 < OO / 4; ++o4) {
        float4 a = A4[o4];
        float4 v = B4[o4];
        int o = o4 * 4;
        float h0 = a.x + v.x, h1 = a.y + v.y, h2 = a.z + v.z, h3 = a.w + v.w;
        stage[(o + 0) * 128 + tid] = fmaxf(__fmaf_rn(h0, ssc[o + 0], ssh[o + 0]), 0.0f);
        stage[(o + 1) * 128 + tid] = fmaxf(__fmaf_rn(h1, ssc[o + 1], ssh[o + 1]), 0.0f);
        stage[(o + 2) * 128 + tid] = fmaxf(__fmaf_rn(h2, ssc[o + 2], ssh[o + 2]), 0.0f);
        stage[(o + 3) * 128 + tid] = fmaxf(__fmaf_rn(h3, ssc[o + 3], ssh[o + 3]), 0.0f);
    }
    __syncthreads();

    const float4* st4 = (const float4*)stage;
    float* ob = out + ((size_t)b * OO) * NKB + e0;
#pragma unroll
    for (int i = tid; i < OO * 32; i += 128) {
        int o  = i >> 5;
        int t4 = i & 31;
        float4 v = st4[o * 32 + t4];
        *(float4*)(ob + (size_t)o * NKB + t4 * 4) = v;
    }
}

// ---------------- launch ----------------
extern "C" void kernel_launch(void* const* d_in, const int* in_sizes, int n_in,
                              void* d_out, int out_size) {
    const float* x     = (const float*)d_in[0];   // (4, 8192, 3) f32
    const float* W     = (const float*)d_in[1];   // (64, 6) f32
    const float* gamma = (const float*)d_in[2];   // (64,) f32
    const float* beta  = (const float*)d_in[3];   // (64,) f32
    float* out = (float*)d_out;                   // (4, 64, 8192, 20) f32

    int* idx_ptr;
    cudaGetSymbolAddress((void**)&idx_ptr, g_idx);

    k_prep<<<PTS / 256, 256>>>(x, W);
    k_knn<<<dim3(NN / 128, BB), 128>>>(idx_ptr);
    k_stats<<<SBLK, OO>>>(idx_ptr);
    k_reduce<<<1, OO>>>(gamma, beta);
    k_out<<<dim3(NKB / 128, BB), 128>>>(idx_ptr, out);
}

// round 5
// speedup vs baseline: 1.2383x; 1.2383x over previous
#include <cuda_runtime.h>
#include <cstdint>

// Problem shape (fixed by the dataset problem)
#define BB 4
#define NN 8192
#define CC 3
#define OO 64
#define KK 20
#define PTS   (BB * NN)          // 32768
#define EDGES (PTS * KK)         // 655360
#define NKB   (NN * KK)          // 163840 edges per batch
#define SBLK  512                // stats partial blocks
#define RR    4                  // knn candidate-range splits
#define RLEN  (NN / RR)          // 2048 candidates per range

#define INF_F __int_as_float(0x7f800000)

// ---------------- device scratch (no allocations allowed) ----------------
__device__ float4 g_cand[PTS];          // (x, y, z, sq)
__device__ float  g_A [PTS * OO];       // x · (W1 - W2)^T   (center contribution)
__device__ float  g_Bv[PTS * OO];       // x · W2^T          (neighbor contribution)
__device__ int    g_idx[EDGES];         // final knn indices
__device__ uint2  g_pk[RR * PTS * KK];  // partial top-20 per range: (d2 bits, idx)
__device__ float  g_part[SBLK * 2 * OO];
__device__ float  g_scale[OO];
__device__ float  g_shift[OO];

// ---------------- helpers ----------------

// Reference-parity distance (do NOT change — rounding-matched to the ref):
//   sq  = fma(x2,x2, fma(x1,x1, x0*x0))
//   dot = fma(z, fma(y, mul(x)))
//   d2  = fma(-2, dot, sqn+sqm)  == fl((sqn+sqm) - 2*dot)  (2*dot exact)
__device__ __forceinline__ float d2f(float qx, float qy, float qz, float sqn,
                                     float4 c) {
    float dot = __fmaf_rn(qz, c.z, __fmaf_rn(qy, c.y, __fmul_rn(qx, c.x)));
    return __fmaf_rn(-2.0f, dot, __fadd_rn(sqn, c.w));
}

// Branchless fully-unrolled sorted insert (ascending). Caller guarantees
// d < kd[KK-1]. Strict < keeps equal-distance elements in scan (index) order.
__device__ __forceinline__ void insert20(float (&kd)[KK], int (&ki)[KK],
                                         float d, int m) {
#pragma unroll
    for (int j = KK - 1; j >= 0; --j) {
        bool ltj = d < kd[j];
        if (ltj) {
            bool ltp = (j > 0) ? (d < kd[j - 1]) : false;
            kd[j] = ltp ? kd[j - 1] : d;
            ki[j] = ltp ? ki[j - 1] : m;
        }
    }
}

// ---------------- kernel 1: per-point precompute ----------------
__global__ void k_prep(const float* __restrict__ x, const float* __restrict__ W) {
    __shared__ float sW[OO * 6];
    int tid = threadIdx.x;
    for (int i = tid; i < OO * 6; i += blockDim.x) sW[i] = W[i];
    __syncthreads();

    int p = blockIdx.x * blockDim.x + tid;
    float x0 = x[p * 3 + 0], x1 = x[p * 3 + 1], x2 = x[p * 3 + 2];
    float sq = __fmaf_rn(x2, x2, __fmaf_rn(x1, x1, __fmul_rn(x0, x0)));
    g_cand[p] = make_float4(x0, x1, x2, sq);

#pragma unroll 8
    for (int o = 0; o < OO; ++o) {
        float w0 = sW[o * 6 + 0], w1 = sW[o * 6 + 1], w2 = sW[o * 6 + 2];
        float w3 = sW[o * 6 + 3], w4 = sW[o * 6 + 4], w5 = sW[o * 6 + 5];
        g_Bv[p * OO + o] = w3 * x0 + w4 * x1 + w5 * x2;
        g_A [p * OO + o] = (w0 - w3) * x0 + (w1 - w4) * x1 + (w2 - w5) * x2;
    }
}

// ---------------- kernel 2: partial kNN over one candidate range ------------
// blockIdx.z selects a 2048-candidate range; each block produces a sorted
// partial top-20 (with distances). 4x the warps of the monolithic version.
__global__ void __launch_bounds__(128) k_knn(void) {
    __shared__ float4 tile[1024];            // 16 KB
    __shared__ uint2  sbuf[128][16];         // 16 KB, per-lane staging buffers

    const int tid = threadIdx.x;
    const int pb  = blockIdx.y * NN;
    const int q   = blockIdx.x * 128 + tid;
    const int r0  = blockIdx.z * RLEN;

    float4 qc = g_cand[pb + q];
    const float qx = qc.x, qy = qc.y, qz = qc.z, sqn = qc.w;

    float kd[KK];
    int   ki[KK];
#pragma unroll
    for (int j = 0; j < KK; ++j) { kd[j] = INF_F; ki[j] = 0; }
    float tau = INF_F;
    int   cnt = 0;

    for (int t0 = r0; t0 < r0 + RLEN; t0 += 1024) {
        __syncthreads();
#pragma unroll
        for (int i = 0; i < 1024; i += 128) tile[i + tid] = g_cand[pb + t0 + i + tid];
        __syncthreads();

        int jstart = 0;
        if (t0 == r0) {
            // warm-up: direct insert of first 32 candidates of this range
            for (int j = 0; j < 32; ++j) {
                float d2 = d2f(qx, qy, qz, sqn, tile[j]);
                if (d2 < kd[KK - 1]) insert20(kd, ki, d2, t0 + j);
            }
            tau = kd[KK - 1];
            jstart = 32;
        }

        for (int j = jstart; j < 1024; j += 8) {
#pragma unroll
            for (int u = 0; u < 8; ++u) {
                float4 c  = tile[j + u];
                float  d2 = d2f(qx, qy, qz, sqn, c);
                if (d2 < tau) {
                    sbuf[tid][cnt] = make_uint2(__float_as_uint(d2),
                                                (unsigned)(t0 + j + u));
                    cnt++;
                }
            }
            if (__any_sync(0xFFFFFFFFu, cnt >= 8)) {
                for (int u2 = 0; u2 < cnt; ++u2) {
                    uint2 e = sbuf[tid][u2];
                    float d = __uint_as_float(e.x);
                    if (d < kd[KK - 1]) insert20(kd, ki, d, (int)e.y);
                }
                cnt = 0;
                tau = kd[KK - 1];
            }
        }
    }
    // drain
    for (int u2 = 0; u2 < cnt; ++u2) {
        uint2 e = sbuf[tid][u2];
        float d = __uint_as_float(e.x);
        if (d < kd[KK - 1]) insert20(kd, ki, d, (int)e.y);
    }

    uint2* op = g_pk + ((size_t)blockIdx.z * PTS + pb + q) * KK;
#pragma unroll
    for (int j = 0; j < KK; ++j)
        op[j] = make_uint2(__float_as_uint(kd[j]), (unsigned)ki[j]);
}

// ---------------- kernel 2b: merge RR sorted partial lists -----------------
// Ranges are index-ascending and each partial list is stable-sorted, so a
// strict-< scan in ascending range order preserves lowest-index tie-breaks.
__global__ void k_merge(int* __restrict__ outidx) {
    int p = blockIdx.x * blockDim.x + threadIdx.x;   // 0..PTS-1

    const uint2* L[RR];
    uint2 head[RR];
    int   pos[RR];
#pragma unroll
    for (int r = 0; r < RR; ++r) {
        L[r]    = g_pk + ((size_t)r * PTS + p) * KK;
        head[r] = __ldg(&L[r][0]);
        pos[r]  = 0;
    }

    int* op = outidx + (size_t)p * KK;
#pragma unroll
    for (int j = 0; j < KK; ++j) {
        float bd = INF_F;
        int   br = 0;
#pragma unroll
        for (int r = 0; r < RR; ++r) {
            float d = __uint_as_float(head[r].x);
            if (d < bd) { bd = d; br = r; }
        }
        op[j] = (int)head[br].y;
        int np = ++pos[br];
        head[br] = (np < KK) ? __ldg(&L[br][np])
                             : make_uint2(__float_as_uint(INF_F), 0u);
    }
}

// ---------------- kernel 3: BN partial stats ----------------
__global__ void k_stats(const int* __restrict__ idx) {
    int o   = threadIdx.x;
    int pn0 = blockIdx.x * (PTS / SBLK);   // 64 rows per block
    float s = 0.0f, s2 = 0.0f;
    for (int pn = pn0; pn < pn0 + (PTS / SBLK); ++pn) {
        float a     = g_A[pn * OO + o];
        int   nbase = (pn >> 13) << 13;    // batch base (NN = 8192)
        const int* ip = idx + pn * KK;
#pragma unroll
        for (int j = 0; j < KK; ++j) {
            int   m = __ldg(ip + j);
            float h = a + g_Bv[(nbase + m) * OO + o];
            s  += h;
            s2  = __fmaf_rn(h, h, s2);
        }
    }
    g_part[blockIdx.x * (2 * OO) + o]      = s;
    g_part[blockIdx.x * (2 * OO) + OO + o] = s2;
}

// ---------------- kernel 4: parallel reduce + BN coefficients ----------------
// 64 blocks (one per channel) x 128 threads; deterministic double tree reduce.
__global__ void k_reduce(const float* __restrict__ gamma,
                         const float* __restrict__ beta) {
    __shared__ double sh[128], sh2[128];
    int o = blockIdx.x;
    int t = threadIdx.x;
    double s = 0.0, s2 = 0.0;
    for (int i = t; i < SBLK; i += 128) {
        s  += (double)g_part[i * (2 * OO) + o];
        s2 += (double)g_part[i * (2 * OO) + OO + o];
    }
    sh[t] = s; sh2[t] = s2;
    __syncthreads();
    for (int w = 64; w > 0; w >>= 1) {
        if (t < w) { sh[t] += sh[t + w]; sh2[t] += sh2[t + w]; }
        __syncthreads();
    }
    if (t == 0) {
        const double cnt = (double)EDGES;
        double mean = sh[0] / cnt;
        double var  = sh2[0] / cnt - mean * mean;   // biased, matches jnp.var
        double sc   = (double)gamma[o] / sqrt(var + 1e-5);
        g_scale[o] = (float)sc;
        g_shift[o] = (float)((double)beta[o] - mean * sc);
    }
}

// ---------------- kernel 5: output (fused conv + BN + relu + transpose) ----
__global__ void __launch_bounds__(128) k_out(const int* __restrict__ idx,
                                             float* __restrict__ out) {
    __shared__ float stage[OO * 128];   // 32 KB
    __shared__ float ssc[OO], ssh[OO];
    int tid = threadIdx.x;
    if (tid < OO) { ssc[tid] = g_scale[tid]; ssh[tid] = g_shift[tid]; }
    __syncthreads();

    int b  = blockIdx.y;
    int e0 = blockIdx.x * 128;          // within-batch edge offset
    int el = e0 + tid;
    int nl = el / KK;
    int j  = el - nl * KK;
    int pn = b * NN + nl;
    int m  = idx[pn * KK + j];

    const float4* A4 = (const float4*)(g_A  + (size_t)pn * OO);
    const float4* B4 = (const float4*)(g_Bv + ((size_t)(b * NN + m)) * OO);

#pragma unroll
    for (int o4 = 0; o4 < OO / 4; ++o4) {
        float4 a = A4[o4];
        float4 v = B4[o4];
        int o = o4 * 4;
        float h0 = a.x + v.x, h1 = a.y + v.y, h2 = a.z + v.z, h3 = a.w + v.w;
        stage[(o + 0) * 128 + tid] = fmaxf(__fmaf_rn(h0, ssc[o + 0], ssh[o + 0]), 0.0f);
        stage[(o + 1) * 128 + tid] = fmaxf(__fmaf_rn(h1, ssc[o + 1], ssh[o + 1]), 0.0f);
        stage[(o + 2) * 128 + tid] = fmaxf(__fmaf_rn(h2, ssc[o + 2], ssh[o + 2]), 0.0f);
        stage[(o + 3) * 128 + tid] = fmaxf(__fmaf_rn(h3, ssc[o + 3], ssh[o + 3]), 0.0f);
    }
    __syncthreads();

    const float4* st4 = (const float4*)stage;
    float* ob = out + ((size_t)b * OO) * NKB + e0;
#pragma unroll
    for (int i = tid; i < OO * 32; i += 128) {
        int o  = i >> 5;
        int t4 = i & 31;
        float4 v = st4[o * 32 + t4];
        *(float4*)(ob + (size_t)o * NKB + t4 * 4) = v;
    }
}

// ---------------- launch ----------------
extern "C" void kernel_launch(void* const* d_in, const int* in_sizes, int n_in,
                              void* d_out, int out_size) {
    const float* x     = (const float*)d_in[0];   // (4, 8192, 3) f32
    const float* W     = (const float*)d_in[1];   // (64, 6) f32
    const float* gamma = (const float*)d_in[2];   // (64,) f32
    const float* beta  = (const float*)d_in[3];   // (64,) f32
    float* out = (float*)d_out;                   // (4, 64, 8192, 20) f32

    int* idx_ptr;
    cudaGetSymbolAddress((void**)&idx_ptr, g_idx);

    k_prep <<<PTS / 256, 256>>>(x, W);
    k_knn  <<<dim3(NN / 128, BB, RR), 128>>>();
    k_merge<<<PTS / 128, 128>>>(idx_ptr);
    k_stats<<<SBLK, OO>>>(idx_ptr);
    k_reduce<<<OO, 128>>>(gamma, beta);
    k_out  <<<dim3(NKB / 128, BB), 128>>>(idx_ptr, out);
}

// round 6
// speedup vs baseline: 1.5266x; 1.2328x over previous
#include <cuda_runtime.h>
#include <cstdint>

// Problem shape (fixed by the dataset problem)
#define BB 4
#define NN 8192
#define CC 3
#define OO 64
#define KK 20
#define PTS   (BB * NN)          // 32768
#define EDGES (PTS * KK)         // 655360
#define NKB   (NN * KK)          // 163840 edges per batch
#define RR    4                  // knn candidate-range splits
#define RLEN  (NN / RR)          // 2048 candidates per range
#define MBLK  64                 // moments partial blocks

#define INF_F __int_as_float(0x7f800000)

// ---------------- device scratch (no allocations allowed) ----------------
__device__ float4 g_cand[PTS];          // (x, y, z, sq)
__device__ float  g_A [PTS * OO];       // x · (W1 - W2)^T   (center contribution)
__device__ float  g_Bv[PTS * OO];       // x · W2^T          (neighbor contribution)
__device__ int    g_idx[EDGES];         // final knn indices
__device__ uint2  g_pk[RR * PTS * KK];  // partial top-20 per range: (d2 bits, idx)
__device__ double g_mom[MBLK * 27];     // per-block moment partials
__device__ float  g_scale[OO];
__device__ float  g_shift[OO];

// ---------------- helpers ----------------

// Reference-parity distance (do NOT change — rounding-matched to the ref):
//   sq  = fma(x2,x2, fma(x1,x1, x0*x0))
//   dot = fma(z, fma(y, mul(x)))
//   d2  = fma(-2, dot, sqn+sqm)  == fl((sqn+sqm) - 2*dot)  (2*dot exact)
__device__ __forceinline__ float d2f(float qx, float qy, float qz, float sqn,
                                     float4 c) {
    float dot = __fmaf_rn(qz, c.z, __fmaf_rn(qy, c.y, __fmul_rn(qx, c.x)));
    return __fmaf_rn(-2.0f, dot, __fadd_rn(sqn, c.w));
}

// Branchless fully-unrolled sorted insert (ascending). Caller guarantees
// d < kd[KK-1]. Strict < keeps equal-distance elements in scan (index) order.
__device__ __forceinline__ void insert20(float (&kd)[KK], int (&ki)[KK],
                                         float d, int m) {
#pragma unroll
    for (int j = KK - 1; j >= 0; --j) {
        bool ltj = d < kd[j];
        if (ltj) {
            bool ltp = (j > 0) ? (d < kd[j - 1]) : false;
            kd[j] = ltp ? kd[j - 1] : d;
            ki[j] = ltp ? ki[j - 1] : m;
        }
    }
}

// ---------------- kernel 1: per-point precompute ----------------
__global__ void k_prep(const float* __restrict__ x, const float* __restrict__ W) {
    __shared__ float sW[OO * 6];
    int tid = threadIdx.x;
    for (int i = tid; i < OO * 6; i += blockDim.x) sW[i] = W[i];
    __syncthreads();

    int p = blockIdx.x * blockDim.x + tid;
    float x0 = x[p * 3 + 0], x1 = x[p * 3 + 1], x2 = x[p * 3 + 2];
    float sq = __fmaf_rn(x2, x2, __fmaf_rn(x1, x1, __fmul_rn(x0, x0)));
    g_cand[p] = make_float4(x0, x1, x2, sq);

#pragma unroll 8
    for (int o = 0; o < OO; ++o) {
        float w0 = sW[o * 6 + 0], w1 = sW[o * 6 + 1], w2 = sW[o * 6 + 2];
        float w3 = sW[o * 6 + 3], w4 = sW[o * 6 + 4], w5 = sW[o * 6 + 5];
        g_Bv[p * OO + o] = w3 * x0 + w4 * x1 + w5 * x2;
        g_A [p * OO + o] = (w0 - w3) * x0 + (w1 - w4) * x1 + (w2 - w5) * x2;
    }
}

// ---------------- kernel 2: partial kNN over one candidate range ------------
// 7 blocks/SM (launch_bounds caps regs) -> all 1024 blocks in ONE wave.
__global__ void __launch_bounds__(128, 7) k_knn(void) {
    __shared__ float4 tile[512];             // 8 KB
    __shared__ uint2  sbuf[128][12];         // 12 KB, per-lane staging buffers

    const int tid = threadIdx.x;
    const int pb  = blockIdx.y * NN;
    const int q   = blockIdx.x * 128 + tid;
    const int r0  = blockIdx.z * RLEN;

    float4 qc = g_cand[pb + q];
    const float qx = qc.x, qy = qc.y, qz = qc.z, sqn = qc.w;

    float kd[KK];
    int   ki[KK];
#pragma unroll
    for (int j = 0; j < KK; ++j) { kd[j] = INF_F; ki[j] = 0; }
    float tau = INF_F;
    int   cnt = 0;

    for (int t0 = r0; t0 < r0 + RLEN; t0 += 512) {
        __syncthreads();
#pragma unroll
        for (int i = 0; i < 512; i += 128) tile[i + tid] = g_cand[pb + t0 + i + tid];
        __syncthreads();

        int jstart = 0;
        if (t0 == r0) {
            // warm-up: direct insert of first 32 candidates of this range
            for (int j = 0; j < 32; ++j) {
                float d2 = d2f(qx, qy, qz, sqn, tile[j]);
                if (d2 < kd[KK - 1]) insert20(kd, ki, d2, t0 + j);
            }
            tau = kd[KK - 1];
            jstart = 32;
        }

        for (int j = jstart; j < 512; j += 4) {
#pragma unroll
            for (int u = 0; u < 4; ++u) {
                float4 c  = tile[j + u];
                float  d2 = d2f(qx, qy, qz, sqn, c);
                if (d2 < tau) {
                    sbuf[tid][cnt] = make_uint2(__float_as_uint(d2),
                                                (unsigned)(t0 + j + u));
                    cnt++;
                }
            }
            if (__any_sync(0xFFFFFFFFu, cnt >= 8)) {
                for (int u2 = 0; u2 < cnt; ++u2) {
                    uint2 e = sbuf[tid][u2];
                    float d = __uint_as_float(e.x);
                    if (d < kd[KK - 1]) insert20(kd, ki, d, (int)e.y);
                }
                cnt = 0;
                tau = kd[KK - 1];
            }
        }
    }
    // drain
    for (int u2 = 0; u2 < cnt; ++u2) {
        uint2 e = sbuf[tid][u2];
        float d = __uint_as_float(e.x);
        if (d < kd[KK - 1]) insert20(kd, ki, d, (int)e.y);
    }

    uint2* op = g_pk + ((size_t)blockIdx.z * PTS + pb + q) * KK;
#pragma unroll
    for (int j = 0; j < KK; ++j)
        op[j] = make_uint2(__float_as_uint(kd[j]), (unsigned)ki[j]);
}

// ---------------- kernel 2b: merge RR sorted partial lists -----------------
__global__ void k_merge(int* __restrict__ outidx) {
    int p = blockIdx.x * blockDim.x + threadIdx.x;   // 0..PTS-1

    const uint2* L[RR];
    uint2 head[RR];
    int   pos[RR];
#pragma unroll
    for (int r = 0; r < RR; ++r) {
        L[r]    = g_pk + ((size_t)r * PTS + p) * KK;
        head[r] = __ldg(&L[r][0]);
        pos[r]  = 0;
    }

    int* op = outidx + (size_t)p * KK;
#pragma unroll
    for (int j = 0; j < KK; ++j) {
        float bd = INF_F;
        int   br = 0;
#pragma unroll
        for (int r = 0; r < RR; ++r) {
            float d = __uint_as_float(head[r].x);
            if (d < bd) { bd = d; br = r; }
        }
        op[j] = (int)head[br].y;
        int np = ++pos[br];
        head[br] = (np < KK) ? __ldg(&L[br][np])
                             : make_uint2(__float_as_uint(INF_F), 0u);
    }
}

// ---------------- kernel 3: BN moments --------------------------------------
// h(edge n->m)_o = P_o.x_n + Q_o.x_m  is linear in 3D coords, so all channel
// sums/sumsqs reduce to 3x3 moments:
//   Sn  = sum_n x_n            Cnn = sum_n x_n x_n^T        (x20 at reduce)
//   Sm  = sum_edges x_m        Cmm = sum_edges x_m x_m^T
//   Cnm = sum_n x_n (sum_j x_mj)^T
// One thread per point; warp+block tree reduce in double (deterministic).
__global__ void __launch_bounds__(512) k_moments(const int* __restrict__ idx) {
    __shared__ double smem[16][27];
    int tid = threadIdx.x;
    int p   = blockIdx.x * 512 + tid;

    float4 qc = g_cand[p];
    int nbase = (p >> 13) << 13;
    const int* ip = idx + p * KK;

    float sx = 0, sy = 0, sz = 0;
    float mxx = 0, myy = 0, mzz = 0, mxy = 0, mxz = 0, myz = 0;
#pragma unroll
    for (int j = 0; j < KK; ++j) {
        int m = __ldg(ip + j);
        float4 c = g_cand[nbase + m];
        sx += c.x; sy += c.y; sz += c.z;
        mxx = __fmaf_rn(c.x, c.x, mxx);
        myy = __fmaf_rn(c.y, c.y, myy);
        mzz = __fmaf_rn(c.z, c.z, mzz);
        mxy = __fmaf_rn(c.x, c.y, mxy);
        mxz = __fmaf_rn(c.x, c.z, mxz);
        myz = __fmaf_rn(c.y, c.z, myz);
    }

    double v[27];
    v[0]  = qc.x; v[1] = qc.y; v[2] = qc.z;                       // Sn
    v[3]  = (double)qc.x * qc.x; v[4] = (double)qc.y * qc.y;      // Cnn
    v[5]  = (double)qc.z * qc.z;
    v[6]  = (double)qc.x * qc.y; v[7] = (double)qc.x * qc.z;
    v[8]  = (double)qc.y * qc.z;
    v[9]  = sx; v[10] = sy; v[11] = sz;                           // Sm
    v[12] = mxx; v[13] = myy; v[14] = mzz;                        // Cmm
    v[15] = mxy; v[16] = mxz; v[17] = myz;
    v[18] = (double)qc.x * sx; v[19] = (double)qc.x * sy;         // Cnm
    v[20] = (double)qc.x * sz;
    v[21] = (double)qc.y * sx; v[22] = (double)qc.y * sy;
    v[23] = (double)qc.y * sz;
    v[24] = (double)qc.z * sx; v[25] = (double)qc.z * sy;
    v[26] = (double)qc.z * sz;

#pragma unroll
    for (int off = 16; off > 0; off >>= 1) {
#pragma unroll
        for (int i = 0; i < 27; ++i)
            v[i] += __shfl_down_sync(0xFFFFFFFFu, v[i], off);
    }
    int w = tid >> 5, l = tid & 31;
    if (l == 0) {
#pragma unroll
        for (int i = 0; i < 27; ++i) smem[w][i] = v[i];
    }
    __syncthreads();
    if (tid < 27) {
        double s = 0.0;
#pragma unroll
        for (int w2 = 0; w2 < 16; ++w2) s += smem[w2][tid];
        g_mom[blockIdx.x * 27 + tid] = s;
    }
}

// ---------------- kernel 4: moments -> BN scale/shift -----------------------
__global__ void k_reduce(const float* __restrict__ W,
                         const float* __restrict__ gamma,
                         const float* __restrict__ beta) {
    __shared__ double sm[27];
    int t = threadIdx.x;   // 64
    if (t < 27) {
        double s = 0.0;
        for (int i = 0; i < MBLK; ++i) s += g_mom[i * 27 + t];
        sm[t] = s;
    }
    __syncthreads();

    double w0 = W[t * 6 + 0], w1 = W[t * 6 + 1], w2 = W[t * 6 + 2];
    double w3 = W[t * 6 + 3], w4 = W[t * 6 + 4], w5 = W[t * 6 + 5];
    double p0 = w0 - w3, p1 = w1 - w4, p2 = w2 - w5;   // P (center)
    double q0 = w3, q1 = w4, q2 = w5;                  // Q (neighbor)

    double sum = 20.0 * (p0 * sm[0] + p1 * sm[1] + p2 * sm[2])
               + q0 * sm[9] + q1 * sm[10] + q2 * sm[11];

    double pcp = p0 * p0 * sm[3] + p1 * p1 * sm[4] + p2 * p2 * sm[5]
               + 2.0 * (p0 * p1 * sm[6] + p0 * p2 * sm[7] + p1 * p2 * sm[8]);
    double qcq = q0 * q0 * sm[12] + q1 * q1 * sm[13] + q2 * q2 * sm[14]
               + 2.0 * (q0 * q1 * sm[15] + q0 * q2 * sm[16] + q1 * q2 * sm[17]);
    double pcq = p0 * (q0 * sm[18] + q1 * sm[19] + q2 * sm[20])
               + p1 * (q0 * sm[21] + q1 * sm[22] + q2 * sm[23])
               + p2 * (q0 * sm[24] + q1 * sm[25] + q2 * sm[26]);
    double sumsq = 20.0 * pcp + 2.0 * pcq + qcq;

    const double cnt = (double)EDGES;
    double mean = sum / cnt;
    double var  = sumsq / cnt - mean * mean;   // biased, matches jnp.var
    double sc   = (double)gamma[t] / sqrt(var + 1e-5);
    g_scale[t] = (float)sc;
    g_shift[t] = (float)((double)beta[t] - mean * sc);
}

// ---------------- kernel 5: output (fused conv + BN + relu + transpose) ----
__global__ void __launch_bounds__(128) k_out(const int* __restrict__ idx,
                                             float* __restrict__ out) {
    __shared__ float stage[OO * 128];   // 32 KB
    __shared__ float ssc[OO], ssh[OO];
    int tid = threadIdx.x;
    if (tid < OO) { ssc[tid] = g_scale[tid]; ssh[tid] = g_shift[tid]; }
    __syncthreads();

    int b  = blockIdx.y;
    int e0 = blockIdx.x * 128;          // within-batch edge offset
    int el = e0 + tid;
    int nl = el / KK;
    int j  = el - nl * KK;
    int pn = b * NN + nl;
    int m  = idx[pn * KK + j];

    const float4* A4 = (const float4*)(g_A  + (size_t)pn * OO);
    const float4* B4 = (const float4*)(g_Bv + ((size_t)(b * NN + m)) * OO);

#pragma unroll
    for (int o4 = 0; o4 < OO / 4; ++o4) {
        float4 a = A4[o4];
        float4 v = B4[o4];
        int o = o4 * 4;
        float h0 = a.x + v.x, h1 = a.y + v.y, h2 = a.z + v.z, h3 = a.w + v.w;
        stage[(o + 0) * 128 + tid] = fmaxf(__fmaf_rn(h0, ssc[o + 0], ssh[o + 0]), 0.0f);
        stage[(o + 1) * 128 + tid] = fmaxf(__fmaf_rn(h1, ssc[o + 1], ssh[o + 1]), 0.0f);
        stage[(o + 2) * 128 + tid] = fmaxf(__fmaf_rn(h2, ssc[o + 2], ssh[o + 2]), 0.0f);
        stage[(o + 3) * 128 + tid] = fmaxf(__fmaf_rn(h3, ssc[o + 3], ssh[o + 3]), 0.0f);
    }
    __syncthreads();

    const float4* st4 = (const float4*)stage;
    float* ob = out + ((size_t)b * OO) * NKB + e0;
#pragma unroll
    for (int i = tid; i < OO * 32; i += 128) {
        int o  = i >> 5;
        int t4 = i & 31;
        float4 v = st4[o * 32 + t4];
        *(float4*)(ob + (size_t)o * NKB + t4 * 4) = v;
    }
}

// ---------------- launch ----------------
extern "C" void kernel_launch(void* const* d_in, const int* in_sizes, int n_in,
                              void* d_out, int out_size) {
    const float* x     = (const float*)d_in[0];   // (4, 8192, 3) f32
    const float* W     = (const float*)d_in[1];   // (64, 6) f32
    const float* gamma = (const float*)d_in[2];   // (64,) f32
    const float* beta  = (const float*)d_in[3];   // (64,) f32
    float* out = (float*)d_out;                   // (4, 64, 8192, 20) f32

    int* idx_ptr;
    cudaGetSymbolAddress((void**)&idx_ptr, g_idx);

    k_prep   <<<PTS / 256, 256>>>(x, W);
    k_knn    <<<dim3(NN / 128, BB, RR), 128>>>();
    k_merge  <<<PTS / 128, 128>>>(idx_ptr);
    k_moments<<<MBLK, 512>>>(idx_ptr);
    k_reduce <<<1, OO>>>(W, gamma, beta);
    k_out    <<<dim3(NKB / 128, BB), 128>>>(idx_ptr, out);
}